// round 4
// baseline (speedup 1.0000x reference)
#include <cuda_runtime.h>

#define BB 32
#define SS 1024
#define DD 512
#define DD4 (DD/4)
#define MAXL 8192   // durations in [1,8], S=1024 -> mel_len <= 8192

// Scratch (no device allocation allowed)
__device__ int g_csum[BB * SS];

// ---------------------------------------------------------------------------
// K1: per-batch inclusive scan of durations (warp-shuffle, 2 barriers).
// Writes g_csum and the mel_len fp32 tail.
// ---------------------------------------------------------------------------
__global__ __launch_bounds__(SS)
void lr_scan_kernel(const int* __restrict__ dur,
                    float* __restrict__ mel_len_out,
                    int has_tail)
{
    __shared__ int warp_sums[32];
    const int b    = blockIdx.x;
    const int tid  = threadIdx.x;
    const int lane = tid & 31;
    const int wid  = tid >> 5;

    int v = dur[b * SS + tid];
    #pragma unroll
    for (int off = 1; off < 32; off <<= 1) {
        int n = __shfl_up_sync(0xffffffff, v, off);
        if (lane >= off) v += n;
    }
    if (lane == 31) warp_sums[wid] = v;
    __syncthreads();
    if (wid == 0) {
        int w = warp_sums[lane];
        #pragma unroll
        for (int off = 1; off < 32; off <<= 1) {
            int n = __shfl_up_sync(0xffffffff, w, off);
            if (lane >= off) w += n;
        }
        warp_sums[lane] = w;
    }
    __syncthreads();
    const int c = v + ((wid > 0) ? warp_sums[wid - 1] : 0);
    g_csum[b * SS + tid] = c;
    if (has_tail && tid == SS - 1) mel_len_out[b] = (float)c;
}

// ---------------------------------------------------------------------------
// K2 (expand, R2 structure): ONE WARP PER OUTPUT ROW.
//  - warp-uniform binary search of g_csum (broadcast loads, L1/L2-hot 4KB row)
//  - lane l handles float4s l, l+32, l+64, l+96: 4x LDG.128 (MLP=4) + 4x STG.128
//  - __stcs streaming stores keep x resident in L2
//  - lane 0 writes the mel_mask float for its row
// ---------------------------------------------------------------------------
__global__ __launch_bounds__(256)
void lr_expand_kernel(const float4* __restrict__ x4,
                      float4*       __restrict__ out4,
                      float*        __restrict__ mask_out,
                      int max_len, int total_rows, int has_tail)
{
    const int row  = (blockIdx.x * blockDim.x + threadIdx.x) >> 5;
    const int lane = threadIdx.x & 31;
    if (row >= total_rows) return;

    const int b = row / max_len;            // warp-uniform
    const int t = row - b * max_len;

    const int* __restrict__ c = g_csum + (b << 10);
    const int mel = __ldg(&c[SS - 1]);

    const long out_base = (long)row * DD4 + lane;

    if (t >= mel) {
        if (has_tail && lane == 0) mask_out[row] = 1.0f;
        const float4 z = make_float4(0.f, 0.f, 0.f, 0.f);
        __stcs(&out4[out_base],      z);
        __stcs(&out4[out_base + 32], z);
        __stcs(&out4[out_base + 64], z);
        __stcs(&out4[out_base + 96], z);
        return;
    }
    if (has_tail && lane == 0) mask_out[row] = 0.0f;

    // first i in [0, S-1] with csum[i] > t (uniform across warp -> broadcast)
    int lo = 0, hi = SS - 1;
    #pragma unroll
    for (int it = 0; it < 10; ++it) {
        if (lo < hi) {
            int mid = (lo + hi) >> 1;
            if (__ldg(&c[mid]) > t) hi = mid; else lo = mid + 1;
        }
    }

    const long in_base = ((long)(b * SS + lo)) * DD4 + lane;
    float4 v0 = __ldg(&x4[in_base]);
    float4 v1 = __ldg(&x4[in_base + 32]);
    float4 v2 = __ldg(&x4[in_base + 64]);
    float4 v3 = __ldg(&x4[in_base + 96]);
    __stcs(&out4[out_base],      v0);
    __stcs(&out4[out_base + 32], v1);
    __stcs(&out4[out_base + 64], v2);
    __stcs(&out4[out_base + 96], v3);
}

// ---------------------------------------------------------------------------
extern "C" void kernel_launch(void* const* d_in, const int* in_sizes, int n_in,
                              void* d_out, int out_size)
{
    const float* x   = (const float*)d_in[0];
    const int*   dur = (const int*)d_in[1];
    float*       out = (float*)d_out;

    // Recover max_len from out_size.
    // Layout A (tuple of 3): out_size = B*L*D + B + B*L  ->  L = (out_size-B)/(B*(D+1))
    // Layout B (expanded only): out_size = B*L*D         ->  L = out_size/(B*D)
    long L;
    int has_tail;
    long os = (long)out_size;
    if ((os - BB) > 0 && ((os - BB) % ((long)BB * (DD + 1))) == 0) {
        L = (os - BB) / ((long)BB * (DD + 1));
        has_tail = 1;
    } else {
        L = os / ((long)BB * DD);
        has_tail = 0;
    }
    if (L <= 0 || L > MAXL) return;

    const int max_len = (int)L;
    float* mel_len_out = out + (long)BB * max_len * DD;   // B floats
    float* mask_out    = mel_len_out + BB;                // B*L floats

    // K1: scan only
    lr_scan_kernel<<<BB, SS>>>(dur, mel_len_out, has_tail);

    // K2: expand (one warp per output row), search fused in
    {
        const int total_rows = BB * max_len;
        const int warps_per_block = 256 / 32;
        const int blocks = (total_rows + warps_per_block - 1) / warps_per_block;
        lr_expand_kernel<<<blocks, 256>>>((const float4*)x, (float4*)out,
                                          mask_out, max_len, total_rows, has_tail);
    }
}

// round 5
// speedup vs baseline: 1.1550x; 1.1550x over previous
#include <cuda_runtime.h>

#define BB 32
#define SS 1024
#define DD 512
#define DD4 (DD/4)
#define MAXL 8192   // durations in [1,8], S=1024 -> mel_len <= 8192
#define CH 8        // idx-build chunks per batch (32*8 = 256 blocks)

// Scratch (no device allocation allowed)
// g_idx[r] = global source row b*S+i, or -1 for padding
__device__ int g_idx[BB * MAXL];

// ---------------------------------------------------------------------------
// K1: fused scan + index build, parallel over 32*CH blocks.
// Each block redundantly scans its batch's durations (warp-shuffle, cheap),
// then builds g_idx + mask for its chunk of output rows via smem search.
// ---------------------------------------------------------------------------
__global__ __launch_bounds__(SS)
void lr_scan_idx_kernel(const int* __restrict__ dur,
                        float* __restrict__ mel_len_out,
                        float* __restrict__ mask_out,
                        int max_len, int rows_pc, int has_tail)
{
    __shared__ int s[SS];
    __shared__ int warp_sums[32];

    const int b     = blockIdx.x >> 3;        // / CH
    const int chunk = blockIdx.x & (CH - 1);  // % CH
    const int tid   = threadIdx.x;
    const int lane  = tid & 31;
    const int wid   = tid >> 5;

    // inclusive scan of durations[b] into smem
    int v = dur[b * SS + tid];
    #pragma unroll
    for (int off = 1; off < 32; off <<= 1) {
        int n = __shfl_up_sync(0xffffffff, v, off);
        if (lane >= off) v += n;
    }
    if (lane == 31) warp_sums[wid] = v;
    __syncthreads();
    if (wid == 0) {
        int w = warp_sums[lane];
        #pragma unroll
        for (int off = 1; off < 32; off <<= 1) {
            int n = __shfl_up_sync(0xffffffff, w, off);
            if (lane >= off) w += n;
        }
        warp_sums[lane] = w;
    }
    __syncthreads();
    s[tid] = v + ((wid > 0) ? warp_sums[wid - 1] : 0);
    __syncthreads();

    const int mel = s[SS - 1];
    if (has_tail && chunk == 0 && tid == 0) mel_len_out[b] = (float)mel;

    const int t0 = chunk * rows_pc;
    const int t1 = min(t0 + rows_pc, max_len);
    for (int t = t0 + tid; t < t1; t += SS) {
        const int r = b * max_len + t;
        if (t >= mel) {
            g_idx[r] = -1;
            if (has_tail) mask_out[r] = 1.0f;
        } else {
            int lo = 0, hi = SS - 1;   // first i with s[i] > t
            #pragma unroll
            for (int it = 0; it < 10; ++it) {
                if (lo < hi) {
                    int mid = (lo + hi) >> 1;
                    if (s[mid] > t) hi = mid; else lo = mid + 1;
                }
            }
            g_idx[r] = b * SS + lo;
            if (has_tail) mask_out[r] = 0.0f;
        }
    }
}

// ---------------------------------------------------------------------------
// K2: streaming gather-expand. ONE WARP PER TWO OUTPUT ROWS (straight-line).
//  - 2 broadcast idx loads, then 8 independent LDG.128 (MLP=8), 8 STG.128
//  - __stcs streaming stores: keep x resident in L2 (output is write-once)
// ---------------------------------------------------------------------------
__global__ __launch_bounds__(256)
void lr_expand_kernel(const float4* __restrict__ x4,
                      float4* __restrict__ out4,
                      int total_rows)
{
    const int pair = (blockIdx.x * blockDim.x + threadIdx.x) >> 5;
    const int lane = threadIdx.x & 31;
    const int row0 = pair * 2;
    if (row0 >= total_rows) return;
    const bool has1 = (row0 + 1) < total_rows;

    const int src0 = g_idx[row0];
    const int src1 = has1 ? g_idx[row0 + 1] : -1;

    const float4 z = make_float4(0.f, 0.f, 0.f, 0.f);
    float4 a0 = z, a1 = z, a2 = z, a3 = z;
    float4 b0 = z, b1 = z, b2 = z, b3 = z;

    if (src0 >= 0) {
        const long ib = (long)src0 * DD4 + lane;
        a0 = __ldg(&x4[ib]);
        a1 = __ldg(&x4[ib + 32]);
        a2 = __ldg(&x4[ib + 64]);
        a3 = __ldg(&x4[ib + 96]);
    }
    if (src1 >= 0) {
        const long ib = (long)src1 * DD4 + lane;
        b0 = __ldg(&x4[ib]);
        b1 = __ldg(&x4[ib + 32]);
        b2 = __ldg(&x4[ib + 64]);
        b3 = __ldg(&x4[ib + 96]);
    }

    const long ob0 = (long)row0 * DD4 + lane;
    __stcs(&out4[ob0],      a0);
    __stcs(&out4[ob0 + 32], a1);
    __stcs(&out4[ob0 + 64], a2);
    __stcs(&out4[ob0 + 96], a3);
    if (has1) {
        const long ob1 = ob0 + DD4;
        __stcs(&out4[ob1],      b0);
        __stcs(&out4[ob1 + 32], b1);
        __stcs(&out4[ob1 + 64], b2);
        __stcs(&out4[ob1 + 96], b3);
    }
}

// ---------------------------------------------------------------------------
extern "C" void kernel_launch(void* const* d_in, const int* in_sizes, int n_in,
                              void* d_out, int out_size)
{
    const float* x   = (const float*)d_in[0];
    const int*   dur = (const int*)d_in[1];
    float*       out = (float*)d_out;

    // Recover max_len from out_size.
    // Layout A (tuple of 3): out_size = B*L*D + B + B*L  ->  L = (out_size-B)/(B*(D+1))
    // Layout B (expanded only): out_size = B*L*D         ->  L = out_size/(B*D)
    long L;
    int has_tail;
    long os = (long)out_size;
    if ((os - BB) > 0 && ((os - BB) % ((long)BB * (DD + 1))) == 0) {
        L = (os - BB) / ((long)BB * (DD + 1));
        has_tail = 1;
    } else {
        L = os / ((long)BB * DD);
        has_tail = 0;
    }
    if (L <= 0 || L > MAXL) return;

    const int max_len = (int)L;
    const int rows_pc = (max_len + CH - 1) / CH;

    float* mel_len_out = out + (long)BB * max_len * DD;   // B floats
    float* mask_out    = mel_len_out + BB;                // B*L floats

    // K1: parallel fused scan + idx build
    lr_scan_idx_kernel<<<BB * CH, SS>>>(dur, mel_len_out, mask_out,
                                        max_len, rows_pc, has_tail);

    // K2: expand, one warp per 2 rows (MLP=8)
    {
        const int total_rows = BB * max_len;
        const int pairs = (total_rows + 1) / 2;
        const int warps_per_block = 256 / 32;
        const int blocks = (pairs + warps_per_block - 1) / warps_per_block;
        lr_expand_kernel<<<blocks, 256>>>((const float4*)x, (float4*)out, total_rows);
    }
}